// round 1
// baseline (speedup 1.0000x reference)
#include <cuda_runtime.h>
#include <math.h>
#include <stdint.h>

// ---------------- problem constants ----------------
#define T_TOK 8192
#define DIM   2048     // hidden
#define IDIM  2048     // intermediate
#define NEXP  8
#define TOPK  2
#define NPAIR (T_TOK*TOPK)            // 16384 token-expert pairs
#define NTILE_MAX (NPAIR/128 + NEXP)  // 136 worst-case M-tiles

// ---------------- device scratch (static; no allocation) ----------------
__device__ int   g_expert[NPAIR];
__device__ float g_weight[NPAIR];
__device__ int   g_cnt[NEXP];
__device__ int   g_cursor[NEXP];
__device__ int   g_tok[NPAIR];     // token id per permuted row
__device__ int   g_pair[NPAIR];    // pair id per permuted row
__device__ int   g_tstart[NTILE_MAX];
__device__ int   g_texp[NTILE_MAX];
__device__ int   g_trows[NTILE_MAX];
__device__ float g_h0[(size_t)NPAIR * IDIM];     // 128 MB
__device__ float g_inter[(size_t)NPAIR * IDIM];  // 128 MB

// ---------------- small kernels ----------------
__global__ void k_reset() {
    int i = threadIdx.x;
    if (i < NEXP) { g_cnt[i] = 0; g_cursor[i] = 0; }
}

__global__ void k_router(const float* __restrict__ logits) {
    int t = blockIdx.x * blockDim.x + threadIdx.x;
    if (t >= T_TOK) return;
    const float* l = logits + t * NEXP;
    float v1 = -1e30f, v2 = -1e30f; int i1 = 0, i2 = 0;
#pragma unroll
    for (int e = 0; e < NEXP; ++e) {
        float v = l[e];
        if (v > v1)      { v2 = v1; i2 = i1; v1 = v; i1 = e; }
        else if (v > v2) { v2 = v;  i2 = e; }
    }
    // softmax over [v1, v2] (v1 is max), then renormalize (matches reference)
    float p  = expf(v2 - v1);
    float s  = 1.0f + p;
    float w1 = 1.0f / s, w2 = p / s;
    float sw = w1 + w2;
    w1 /= sw; w2 /= sw;
    g_expert[2*t]   = i1; g_expert[2*t+1] = i2;
    g_weight[2*t]   = w1; g_weight[2*t+1] = w2;
    atomicAdd(&g_cnt[i1], 1);
    atomicAdd(&g_cnt[i2], 1);
}

__global__ void k_schedule() {
    if (threadIdx.x != 0 || blockIdx.x != 0) return;
    int off = 0, nt = 0;
    for (int e = 0; e < NEXP; ++e) {
        int c = g_cnt[e];
        g_cursor[e] = off;
        for (int s = 0; s < c; s += 128) {
            g_tstart[nt] = off + s;
            g_texp[nt]   = e;
            g_trows[nt]  = (c - s < 128) ? (c - s) : 128;
            nt++;
        }
        off += c;
    }
    for (int i = nt; i < NTILE_MAX; ++i) g_trows[i] = 0;
}

__global__ void k_scatter() {
    int p = blockIdx.x * blockDim.x + threadIdx.x;
    if (p >= NPAIR) return;
    int e   = g_expert[p];
    int dst = atomicAdd(&g_cursor[e], 1);
    g_tok[dst]  = p >> 1;
    g_pair[dst] = p;
}

__global__ void k_zero(float* __restrict__ p, int n) {
    int i = blockIdx.x * blockDim.x + threadIdx.x;
    if (i < n) p[i] = 0.0f;
}

// ---------------- packed f32x2 FMA helpers (2x fp32 throughput on sm_103a) ----
__device__ __forceinline__ double dup2(float a) {
    double r;
    asm("mov.b64 %0, {%1, %1};" : "=d"(r) : "f"(a));
    return r;
}
__device__ __forceinline__ double ffma2(double c, double a, double b) {
    double r;
    asm("fma.rn.f32x2 %0, %1, %2, %3;" : "=d"(r) : "d"(a), "d"(b), "d"(c));
    return r;
}

// ---------------- grouped GEMM: 128x128 tile, K-step 8, 256 threads, 8x8/thread
// MODE 0: h0 = gather(X) @ wi0[e]           -> g_h0
// MODE 1: h1 = gather(X) @ wi1[e]; epilogue -> g_inter = silu(g_h0) * h1
// MODE 2: out_pairs = g_inter @ wo[e]; epilogue -> atomicAdd(d_out, w * val)
template<int MODE>
__global__ void __launch_bounds__(256, 2) k_gemm(
    const float* __restrict__ Asrc,   // inputs (modes 0/1); ignored in mode 2
    const float* __restrict__ Wsrc,   // wi0 / wi1 / wo
    float* __restrict__ Cdst)         // d_out (mode 2); ignored in modes 0/1
{
    __shared__ alignas(16) float As[2][8][128];
    __shared__ alignas(16) float Bs[2][8][128];

    const int bx = blockIdx.x, by = blockIdx.y;
    const int rows = g_trows[bx];
    if (rows == 0) return;
    const int rs = g_tstart[bx];
    const int e  = g_texp[bx];
    const float* __restrict__ B = Wsrc + (size_t)e * 2048 * 2048;

    const int tid = threadIdx.x;
    const int aM  = tid >> 1;          // row within tile for A loads
    const int aK  = (tid & 1) * 4;     // k offset for A loads
    const int bK  = tid >> 5;          // k row for B loads
    const int bN  = (tid & 31) * 4;    // n offset for B loads
    const int ty8 = (tid >> 4) * 8;    // compute row base
    const int tx8 = (tid & 15) * 8;    // compute col base

    const bool avalid = aM < rows;
    const float* arow;
    if (MODE == 2) {
        arow = g_inter + (size_t)(rs + aM) * IDIM;
    } else {
        int tok = avalid ? g_tok[rs + aM] : 0;
        arow = Asrc + (size_t)tok * DIM;
    }
    const float* brow = B + (size_t)bK * 2048 + by * 128 + bN;

    double c[8][4];
#pragma unroll
    for (int i = 0; i < 8; ++i)
#pragma unroll
        for (int j = 0; j < 4; ++j) c[i][j] = 0.0;

    // preload k-tile 0
    {
        float4 av = avalid ? *(const float4*)(arow + aK) : make_float4(0,0,0,0);
        float4 bv = *(const float4*)(brow);
        As[0][aK+0][aM] = av.x; As[0][aK+1][aM] = av.y;
        As[0][aK+2][aM] = av.z; As[0][aK+3][aM] = av.w;
        *(float4*)&Bs[0][bK][bN] = bv;
    }
    __syncthreads();

    const int nk = 2048 / 8;
    int cur = 0;
    for (int kt = 0; kt < nk; ++kt) {
        float4 av, bv;
        const bool pf = (kt + 1 < nk);
        if (pf) {
            int k0 = (kt + 1) * 8;
            av = avalid ? *(const float4*)(arow + k0 + aK) : make_float4(0,0,0,0);
            bv = *(const float4*)(brow + (size_t)k0 * 2048);
        }
#pragma unroll
        for (int kk = 0; kk < 8; ++kk) {
            const float4  a0  = *(const float4*) &As[cur][kk][ty8];
            const float4  a1  = *(const float4*) &As[cur][kk][ty8 + 4];
            const double2 b01 = *(const double2*)&Bs[cur][kk][tx8];
            const double2 b23 = *(const double2*)&Bs[cur][kk][tx8 + 4];
#define MOE_ROW(i, aval) { double ad = dup2(aval);                         \
            c[i][0] = ffma2(c[i][0], ad, b01.x);                           \
            c[i][1] = ffma2(c[i][1], ad, b01.y);                           \
            c[i][2] = ffma2(c[i][2], ad, b23.x);                           \
            c[i][3] = ffma2(c[i][3], ad, b23.y); }
            MOE_ROW(0, a0.x) MOE_ROW(1, a0.y) MOE_ROW(2, a0.z) MOE_ROW(3, a0.w)
            MOE_ROW(4, a1.x) MOE_ROW(5, a1.y) MOE_ROW(6, a1.z) MOE_ROW(7, a1.w)
#undef MOE_ROW
        }
        if (pf) {
            int nb = cur ^ 1;
            As[nb][aK+0][aM] = av.x; As[nb][aK+1][aM] = av.y;
            As[nb][aK+2][aM] = av.z; As[nb][aK+3][aM] = av.w;
            *(float4*)&Bs[nb][bK][bN] = bv;
        }
        __syncthreads();
        cur ^= 1;
    }

    // ---------------- epilogue ----------------
#pragma unroll
    for (int i = 0; i < 8; ++i) {
        int r = ty8 + i;
        if (r >= rows) break;
        int grow = rs + r;
        if (MODE == 0) {
            float* dst = g_h0 + (size_t)grow * IDIM + by * 128 + tx8;
#pragma unroll
            for (int j = 0; j < 4; ++j)
                *(float2*)(dst + 2*j) = *(float2*)&c[i][j];
        } else if (MODE == 1) {
            size_t base = (size_t)grow * IDIM + by * 128 + tx8;
            const float* h0p = g_h0 + base;
            float* dst = g_inter + base;
#pragma unroll
            for (int j = 0; j < 4; ++j) {
                float2 h = *(const float2*)(h0p + 2*j);
                float2 v = *(float2*)&c[i][j];
                float2 o;
                o.x = (h.x / (1.0f + expf(-h.x))) * v.x;
                o.y = (h.y / (1.0f + expf(-h.y))) * v.y;
                *(float2*)(dst + 2*j) = o;
            }
        } else {
            int pr   = g_pair[grow];
            float w  = g_weight[pr];
            int tok  = pr >> 1;
            float* dst = Cdst + (size_t)tok * DIM + by * 128 + tx8;
#pragma unroll
            for (int j = 0; j < 4; ++j) {
                float2 v = *(float2*)&c[i][j];
                atomicAdd(dst + 2*j,     w * v.x);
                atomicAdd(dst + 2*j + 1, w * v.y);
            }
        }
    }
}

// ---------------- launch ----------------
extern "C" void kernel_launch(void* const* d_in, const int* in_sizes, int n_in,
                              void* d_out, int out_size) {
    const float* inputs = (const float*)d_in[0];
    const float* logits = (const float*)d_in[1];
    const float* wi0    = (const float*)d_in[2];
    const float* wi1    = (const float*)d_in[3];
    const float* wo     = (const float*)d_in[4];
    float* out = (float*)d_out;

    k_reset<<<1, 32>>>();
    k_router<<<(T_TOK + 255) / 256, 256>>>(logits);
    k_schedule<<<1, 1>>>();
    k_scatter<<<(NPAIR + 255) / 256, 256>>>();
    k_zero<<<(T_TOK * DIM + 255) / 256, 256>>>(out, T_TOK * DIM);

    dim3 grid(NTILE_MAX, 2048 / 128);
    k_gemm<0><<<grid, 256>>>(inputs, wi0, out);
    k_gemm<1><<<grid, 256>>>(inputs, wi1, out);
    k_gemm<2><<<grid, 256>>>(inputs, wo,  out);
}

// round 2
// speedup vs baseline: 1.0002x; 1.0002x over previous
#include <cuda_runtime.h>
#include <math.h>
#include <stdint.h>

// ---------------- problem constants ----------------
#define T_TOK 8192
#define DIM   2048     // hidden
#define IDIM  2048     // intermediate
#define NEXP  8
#define TOPK  2
#define NPAIR (T_TOK*TOPK)            // 16384 token-expert pairs
#define NTILE_MAX (NPAIR/128 + NEXP)  // 136 worst-case M-tiles

// ---------------- device scratch (static; no allocation) ----------------
__device__ int   g_expert[NPAIR];
__device__ float g_weight[NPAIR];
__device__ int   g_cnt[NEXP];
__device__ int   g_cursor[NEXP];
__device__ int   g_tok[NPAIR];     // token id per permuted row
__device__ int   g_pair[NPAIR];    // pair id per permuted row
__device__ int   g_tstart[NTILE_MAX];
__device__ int   g_texp[NTILE_MAX];
__device__ int   g_trows[NTILE_MAX];
__device__ float g_h0[(size_t)NPAIR * IDIM];     // 128 MB
__device__ float g_inter[(size_t)NPAIR * IDIM];  // 128 MB

// ---------------- small kernels ----------------
__global__ void k_reset() {
    int i = threadIdx.x;
    if (i < NEXP) { g_cnt[i] = 0; g_cursor[i] = 0; }
}

__global__ void k_router(const float* __restrict__ logits) {
    int t = blockIdx.x * blockDim.x + threadIdx.x;
    if (t >= T_TOK) return;
    const float* l = logits + t * NEXP;
    float v1 = -1e30f, v2 = -1e30f; int i1 = 0, i2 = 0;
#pragma unroll
    for (int e = 0; e < NEXP; ++e) {
        float v = l[e];
        if (v > v1)      { v2 = v1; i2 = i1; v1 = v; i1 = e; }
        else if (v > v2) { v2 = v;  i2 = e; }
    }
    // softmax over [v1, v2] (v1 is max), then renormalize (matches reference)
    float p  = expf(v2 - v1);
    float s  = 1.0f + p;
    float w1 = 1.0f / s, w2 = p / s;
    float sw = w1 + w2;
    w1 /= sw; w2 /= sw;
    g_expert[2*t]   = i1; g_expert[2*t+1] = i2;
    g_weight[2*t]   = w1; g_weight[2*t+1] = w2;
    atomicAdd(&g_cnt[i1], 1);
    atomicAdd(&g_cnt[i2], 1);
}

__global__ void k_schedule() {
    if (threadIdx.x != 0 || blockIdx.x != 0) return;
    int off = 0, nt = 0;
    for (int e = 0; e < NEXP; ++e) {
        int c = g_cnt[e];
        g_cursor[e] = off;
        for (int s = 0; s < c; s += 128) {
            g_tstart[nt] = off + s;
            g_texp[nt]   = e;
            g_trows[nt]  = (c - s < 128) ? (c - s) : 128;
            nt++;
        }
        off += c;
    }
    for (int i = nt; i < NTILE_MAX; ++i) g_trows[i] = 0;
}

__global__ void k_scatter() {
    int p = blockIdx.x * blockDim.x + threadIdx.x;
    if (p >= NPAIR) return;
    int e   = g_expert[p];
    int dst = atomicAdd(&g_cursor[e], 1);
    g_tok[dst]  = p >> 1;
    g_pair[dst] = p;
}

__global__ void k_zero(float* __restrict__ p, int n) {
    int i = blockIdx.x * blockDim.x + threadIdx.x;
    if (i < n) p[i] = 0.0f;
}

// ---------------- packed f32x2 FMA helpers (2x fp32 throughput on sm_103a) ----
__device__ __forceinline__ double dup2(float a) {
    double r;
    asm("mov.b64 %0, {%1, %1};" : "=d"(r) : "f"(a));
    return r;
}
__device__ __forceinline__ double ffma2(double c, double a, double b) {
    double r;
    asm("fma.rn.f32x2 %0, %1, %2, %3;" : "=d"(r) : "d"(a), "d"(b), "d"(c));
    return r;
}

// ---------------- grouped GEMM: 128x128 tile, K-step 8, 256 threads, 8x8/thread
// MODE 0: h0 = gather(X) @ wi0[e]           -> g_h0
// MODE 1: h1 = gather(X) @ wi1[e]; epilogue -> g_inter = silu(g_h0) * h1
// MODE 2: out_pairs = g_inter @ wo[e]; epilogue -> atomicAdd(d_out, w * val)
template<int MODE>
__global__ void __launch_bounds__(256, 2) k_gemm(
    const float* __restrict__ Asrc,   // inputs (modes 0/1); ignored in mode 2
    const float* __restrict__ Wsrc,   // wi0 / wi1 / wo
    float* __restrict__ Cdst)         // d_out (mode 2); ignored in modes 0/1
{
    __shared__ alignas(16) float As[2][8][128];
    __shared__ alignas(16) float Bs[2][8][128];

    const int bx = blockIdx.x, by = blockIdx.y;
    const int rows = g_trows[bx];
    if (rows == 0) return;
    const int rs = g_tstart[bx];
    const int e  = g_texp[bx];
    const float* __restrict__ B = Wsrc + (size_t)e * 2048 * 2048;

    const int tid = threadIdx.x;
    const int aM  = tid >> 1;          // row within tile for A loads
    const int aK  = (tid & 1) * 4;     // k offset for A loads
    const int bK  = tid >> 5;          // k row for B loads
    const int bN  = (tid & 31) * 4;    // n offset for B loads
    const int ty8 = (tid >> 4) * 8;    // compute row base
    const int tx8 = (tid & 15) * 8;    // compute col base

    const bool avalid = aM < rows;
    const float* arow;
    if (MODE == 2) {
        arow = g_inter + (size_t)(rs + aM) * IDIM;
    } else {
        int tok = avalid ? g_tok[rs + aM] : 0;
        arow = Asrc + (size_t)tok * DIM;
    }
    const float* brow = B + (size_t)bK * 2048 + by * 128 + bN;

    double c[8][4];
#pragma unroll
    for (int i = 0; i < 8; ++i)
#pragma unroll
        for (int j = 0; j < 4; ++j) c[i][j] = 0.0;

    // preload k-tile 0
    {
        float4 av = avalid ? *(const float4*)(arow + aK) : make_float4(0,0,0,0);
        float4 bv = *(const float4*)(brow);
        As[0][aK+0][aM] = av.x; As[0][aK+1][aM] = av.y;
        As[0][aK+2][aM] = av.z; As[0][aK+3][aM] = av.w;
        *(float4*)&Bs[0][bK][bN] = bv;
    }
    __syncthreads();

    const int nk = 2048 / 8;
    int cur = 0;
    for (int kt = 0; kt < nk; ++kt) {
        float4 av, bv;
        const bool pf = (kt + 1 < nk);
        if (pf) {
            int k0 = (kt + 1) * 8;
            av = avalid ? *(const float4*)(arow + k0 + aK) : make_float4(0,0,0,0);
            bv = *(const float4*)(brow + (size_t)k0 * 2048);
        }
#pragma unroll
        for (int kk = 0; kk < 8; ++kk) {
            const float4  a0  = *(const float4*) &As[cur][kk][ty8];
            const float4  a1  = *(const float4*) &As[cur][kk][ty8 + 4];
            const double2 b01 = *(const double2*)&Bs[cur][kk][tx8];
            const double2 b23 = *(const double2*)&Bs[cur][kk][tx8 + 4];
#define MOE_ROW(i, aval) { double ad = dup2(aval);                         \
            c[i][0] = ffma2(c[i][0], ad, b01.x);                           \
            c[i][1] = ffma2(c[i][1], ad, b01.y);                           \
            c[i][2] = ffma2(c[i][2], ad, b23.x);                           \
            c[i][3] = ffma2(c[i][3], ad, b23.y); }
            MOE_ROW(0, a0.x) MOE_ROW(1, a0.y) MOE_ROW(2, a0.z) MOE_ROW(3, a0.w)
            MOE_ROW(4, a1.x) MOE_ROW(5, a1.y) MOE_ROW(6, a1.z) MOE_ROW(7, a1.w)
#undef MOE_ROW
        }
        if (pf) {
            int nb = cur ^ 1;
            As[nb][aK+0][aM] = av.x; As[nb][aK+1][aM] = av.y;
            As[nb][aK+2][aM] = av.z; As[nb][aK+3][aM] = av.w;
            *(float4*)&Bs[nb][bK][bN] = bv;
        }
        __syncthreads();
        cur ^= 1;
    }

    // ---------------- epilogue ----------------
#pragma unroll
    for (int i = 0; i < 8; ++i) {
        int r = ty8 + i;
        if (r >= rows) break;
        int grow = rs + r;
        if (MODE == 0) {
            float* dst = g_h0 + (size_t)grow * IDIM + by * 128 + tx8;
#pragma unroll
            for (int j = 0; j < 4; ++j)
                *(float2*)(dst + 2*j) = *(float2*)&c[i][j];
        } else if (MODE == 1) {
            size_t base = (size_t)grow * IDIM + by * 128 + tx8;
            const float* h0p = g_h0 + base;
            float* dst = g_inter + base;
#pragma unroll
            for (int j = 0; j < 4; ++j) {
                float2 h = *(const float2*)(h0p + 2*j);
                float2 v = *(float2*)&c[i][j];
                float2 o;
                o.x = (h.x / (1.0f + expf(-h.x))) * v.x;
                o.y = (h.y / (1.0f + expf(-h.y))) * v.y;
                *(float2*)(dst + 2*j) = o;
            }
        } else {
            int pr   = g_pair[grow];
            float w  = g_weight[pr];
            int tok  = pr >> 1;
            float* dst = Cdst + (size_t)tok * DIM + by * 128 + tx8;
#pragma unroll
            for (int j = 0; j < 4; ++j) {
                float2 v = *(float2*)&c[i][j];
                atomicAdd(dst + 2*j,     w * v.x);
                atomicAdd(dst + 2*j + 1, w * v.y);
            }
        }
    }
}

// ---------------- launch ----------------
extern "C" void kernel_launch(void* const* d_in, const int* in_sizes, int n_in,
                              void* d_out, int out_size) {
    const float* inputs = (const float*)d_in[0];
    const float* logits = (const float*)d_in[1];
    const float* wi0    = (const float*)d_in[2];
    const float* wi1    = (const float*)d_in[3];
    const float* wo     = (const float*)d_in[4];
    float* out = (float*)d_out;

    k_reset<<<1, 32>>>();
    k_router<<<(T_TOK + 255) / 256, 256>>>(logits);
    k_schedule<<<1, 1>>>();
    k_scatter<<<(NPAIR + 255) / 256, 256>>>();
    k_zero<<<(T_TOK * DIM + 255) / 256, 256>>>(out, T_TOK * DIM);

    dim3 grid(NTILE_MAX, 2048 / 128);
    k_gemm<0><<<grid, 256>>>(inputs, wi0, out);
    k_gemm<1><<<grid, 256>>>(inputs, wi1, out);
    k_gemm<2><<<grid, 256>>>(inputs, wo,  out);
}

// round 4
// speedup vs baseline: 2.2407x; 2.2402x over previous
#include <cuda_runtime.h>
#include <cuda_bf16.h>
#include <math.h>
#include <stdint.h>

#define T_TOK 8192
#define DIM   2048
#define IDIM  2048
#define NEXP  8
#define NPAIR 16384
#define NTMAX 136
#define KC    64
#define NKCH  32
#define TB    16384        // one 128x64 bf16 tile, 128B rows
#define GSMEM (8*TB + 1024)

// ---------------- device scratch ----------------
__device__ int   g_expert[NPAIR];
__device__ float g_weight[NPAIR];
__device__ int   g_cnt[NEXP], g_cursor[NEXP];
__device__ int   g_tok[NPAIR], g_pos[NPAIR];
__device__ int   g_tstart[NTMAX], g_texp[NTMAX], g_trows[NTMAX];
__device__ __align__(16) __nv_bfloat16 g_xph[(size_t)NPAIR*DIM];
__device__ __align__(16) __nv_bfloat16 g_xpl[(size_t)NPAIR*DIM];
__device__ __align__(16) __nv_bfloat16 g_w0h[(size_t)NEXP*DIM*IDIM];
__device__ __align__(16) __nv_bfloat16 g_w0l[(size_t)NEXP*DIM*IDIM];
__device__ __align__(16) __nv_bfloat16 g_w1h[(size_t)NEXP*DIM*IDIM];
__device__ __align__(16) __nv_bfloat16 g_w1l[(size_t)NEXP*DIM*IDIM];
__device__ __align__(16) __nv_bfloat16 g_woh[(size_t)NEXP*DIM*IDIM];
__device__ __align__(16) __nv_bfloat16 g_wol[(size_t)NEXP*DIM*IDIM];
__device__ __align__(16) __nv_bfloat16 g_ih[(size_t)NPAIR*IDIM];
__device__ __align__(16) __nv_bfloat16 g_il[(size_t)NPAIR*IDIM];
__device__ __align__(16) float g_h0[(size_t)NPAIR*IDIM];
__device__ __align__(16) float g_op[(size_t)NPAIR*DIM];

// ---------------- helpers ----------------
__device__ __forceinline__ uint32_t s2u(const void* p) {
    uint32_t a;
    asm("{ .reg .u64 t; cvta.to.shared.u64 t, %1; cvt.u32.u64 %0, t; }" : "=r"(a) : "l"(p));
    return a;
}
__device__ __forceinline__ uint32_t sw(uint32_t o) { return o ^ ((o >> 3) & 0x70); }

#define CP16(dst, src) asm volatile("cp.async.cg.shared.global [%0], [%1], 16;" \
                                    :: "r"(dst), "l"(src) : "memory")
#define CP_COMMIT() asm volatile("cp.async.commit_group;" ::: "memory")
#define CP_WAIT1()  asm volatile("cp.async.wait_group 1;" ::: "memory")

#define LDSM4(r0,r1,r2,r3,a) asm volatile( \
    "ldmatrix.sync.aligned.m8n8.x4.shared.b16 {%0,%1,%2,%3}, [%4];" \
    : "=r"(r0),"=r"(r1),"=r"(r2),"=r"(r3) : "r"(a))
#define LDSM2(r0,r1,a) asm volatile( \
    "ldmatrix.sync.aligned.m8n8.x2.shared.b16 {%0,%1}, [%2];" \
    : "=r"(r0),"=r"(r1) : "r"(a))
#define MMA(cc, A, B) asm volatile( \
    "mma.sync.aligned.m16n8k16.row.col.f32.bf16.bf16.f32 " \
    "{%0,%1,%2,%3}, {%4,%5,%6,%7}, {%8,%9}, {%0,%1,%2,%3};" \
    : "+f"(cc[0]),"+f"(cc[1]),"+f"(cc[2]),"+f"(cc[3]) \
    : "r"(A[0]),"r"(A[1]),"r"(A[2]),"r"(A[3]),"r"(B[0]),"r"(B[1]))

// ---------------- small kernels ----------------
__global__ void k_reset() {
    int i = threadIdx.x;
    if (i < NEXP) { g_cnt[i] = 0; g_cursor[i] = 0; }
}
__global__ void k_router(const float* __restrict__ logits) {
    int t = blockIdx.x * blockDim.x + threadIdx.x;
    if (t >= T_TOK) return;
    const float* l = logits + t * NEXP;
    float v1 = -1e30f, v2 = -1e30f; int i1 = 0, i2 = 0;
#pragma unroll
    for (int e = 0; e < NEXP; ++e) {
        float v = l[e];
        if (v > v1)      { v2 = v1; i2 = i1; v1 = v; i1 = e; }
        else if (v > v2) { v2 = v;  i2 = e; }
    }
    float p = expf(v2 - v1);
    float s = 1.0f + p;
    float w1 = 1.0f / s, w2 = p / s;
    float swn = w1 + w2; w1 /= swn; w2 /= swn;
    g_expert[2*t] = i1; g_expert[2*t+1] = i2;
    g_weight[2*t] = w1; g_weight[2*t+1] = w2;
    atomicAdd(&g_cnt[i1], 1);
    atomicAdd(&g_cnt[i2], 1);
}
__global__ void k_schedule() {
    if (threadIdx.x || blockIdx.x) return;
    int off = 0, nt = 0;
    for (int e = 0; e < NEXP; ++e) {
        int c = g_cnt[e];
        g_cursor[e] = off;
        for (int s = 0; s < c; s += 128) {
            g_tstart[nt] = off + s; g_texp[nt] = e;
            g_trows[nt] = (c - s < 128) ? (c - s) : 128; nt++;
        }
        off += c;
    }
    for (int i = nt; i < NTMAX; ++i) g_trows[i] = 0;
}
__global__ void k_scatter() {
    int p = blockIdx.x * blockDim.x + threadIdx.x;
    if (p >= NPAIR) return;
    int dst = atomicAdd(&g_cursor[g_expert[p]], 1);
    g_tok[dst] = p >> 1;
    g_pos[p]   = dst;
}
__global__ void k_permx(const float* __restrict__ X) {
    int dst = blockIdx.x;
    const float2* src = (const float2*)(X + (size_t)g_tok[dst] * DIM);
    __nv_bfloat162* dh = (__nv_bfloat162*)(g_xph + (size_t)dst * DIM);
    __nv_bfloat162* dl = (__nv_bfloat162*)(g_xpl + (size_t)dst * DIM);
    for (int c = threadIdx.x; c < DIM/2; c += blockDim.x) {
        float2 v = src[c];
        __nv_bfloat162 h = __floats2bfloat162_rn(v.x, v.y);
        dh[c] = h;
        dl[c] = __floats2bfloat162_rn(v.x - __bfloat162float(h.x),
                                      v.y - __bfloat162float(h.y));
    }
}
// transpose + split: W[e][k][n] -> T[e][n][k] bf16 hi/lo
template<int S>
__global__ void k_convw(const float* __restrict__ W) {
    __nv_bfloat16* Th = (S == 0) ? g_w0h : (S == 1) ? g_w1h : g_woh;
    __nv_bfloat16* Tl = (S == 0) ? g_w0l : (S == 1) ? g_w1l : g_wol;
    __shared__ float s[32][33];
    int e = blockIdx.z, k0 = blockIdx.x * 32, n0 = blockIdx.y * 32;
    const float* src = W + (size_t)e * DIM * IDIM;
    int tx = threadIdx.x & 31, ty = threadIdx.x >> 5;
#pragma unroll
    for (int i = 0; i < 4; ++i)
        s[ty + i*8][tx] = src[(size_t)(k0 + ty + i*8) * IDIM + n0 + tx];
    __syncthreads();
#pragma unroll
    for (int i = 0; i < 4; ++i) {
        int n = n0 + ty + i*8, k = k0 + tx;
        float x = s[tx][ty + i*8];
        __nv_bfloat16 h = __float2bfloat16_rn(x);
        size_t o = (size_t)e * DIM * IDIM + (size_t)n * DIM + k;
        Th[o] = h;
        Tl[o] = __float2bfloat16_rn(x - __bfloat162float(h));
    }
}
__global__ void k_combine(float* __restrict__ out) {
    int t = blockIdx.x;
    float w0 = g_weight[2*t], w1 = g_weight[2*t+1];
    const float4* r0 = (const float4*)(g_op + (size_t)g_pos[2*t]   * DIM);
    const float4* r1 = (const float4*)(g_op + (size_t)g_pos[2*t+1] * DIM);
    float4* o = (float4*)(out + (size_t)t * DIM);
    for (int c = threadIdx.x; c < DIM/4; c += blockDim.x) {
        float4 a = r0[c], b = r1[c];
        o[c] = make_float4(w0*a.x + w1*b.x, w0*a.y + w1*b.y,
                           w0*a.z + w1*b.z, w0*a.w + w1*b.w);
    }
}

// ---------------- bf16 hi/lo mma.sync grouped GEMM ----------------
// C = A @ B^T over K=2048; A [NPAIR rows, K] hi/lo, B [2048 n, K] hi/lo per expert.
// MODE 0: A=xp, B=w0 -> g_h0 (fp32)
// MODE 1: A=xp, B=w1 -> inter = silu(h0)*h1 -> g_ih/g_il (bf16 hi/lo)
// MODE 2: A=inter, B=wo -> g_op (fp32)
template<int MODE>
__global__ void __launch_bounds__(256, 1) k_mma() {
    extern __shared__ char smem[];
    const int tid = threadIdx.x, lane = tid & 31, wid = tid >> 5;
    const int bx = blockIdx.x, by = blockIdx.y;
    const int rows = g_trows[bx];
    if (rows == 0) return;
    const int rs = g_tstart[bx], e = g_texp[bx];
    const uint32_t sb = (s2u(smem) + 1023) & ~1023u;

    const __nv_bfloat16 *Ah, *Al, *Bh, *Bl;
    const size_t eo = (size_t)e * DIM * IDIM;
    if (MODE == 2) { Ah = g_ih; Al = g_il; Bh = g_woh + eo; Bl = g_wol + eo; }
    else if (MODE == 1) { Ah = g_xph; Al = g_xpl; Bh = g_w1h + eo; Bl = g_w1l + eo; }
    else { Ah = g_xph; Al = g_xpl; Bh = g_w0h + eo; Bl = g_w0l + eo; }

    // ---- loader geometry: thread -> (row = tid>>1, 64B half = tid&1)
    const int lr = tid >> 1, lc = (tid & 1) * 4;   // lc: 16B-unit index (4 units)
    uint32_t ldo[4];
#pragma unroll
    for (int j = 0; j < 4; ++j) ldo[j] = sw(lr*128 + (lc + j)*16);
    int arow = rs + lr; if (arow > NPAIR-1) arow = NPAIR-1;
    const size_t aoff = (size_t)arow * 2048 + lc*8;
    const size_t boff = (size_t)(by*128 + lr) * 2048 + lc*8;

#define LOADST(stg, kt) { uint32_t st = sb + (stg)*4*TB; int k0 = (kt)*KC;      \
    _Pragma("unroll") for (int j = 0; j < 4; ++j) {                             \
        CP16(st        + ldo[j], Ah + aoff + k0 + j*8);                         \
        CP16(st +   TB + ldo[j], Al + aoff + k0 + j*8);                         \
        CP16(st + 2*TB + ldo[j], Bh + boff + k0 + j*8);                         \
        CP16(st + 3*TB + ldo[j], Bl + boff + k0 + j*8); } }

    // ---- mma geometry: warp (wm, wn), warp tile 64x32
    const int wm = wid & 1, wn = wid >> 1;
    const uint32_t a_row = wm*64 + (lane & 7) + ((lane >> 3) & 1)*8;
    const uint32_t a_kb  = ((lane >> 4) & 1) * 16;
    const int lb = lane & 15;
    const uint32_t b_row = wn*32 + (lb & 7);
    const uint32_t b_kb  = ((lb >> 3) & 1) * 16;

    float c[4][4][4];
#pragma unroll
    for (int m = 0; m < 4; ++m)
#pragma unroll
        for (int n = 0; n < 4; ++n)
#pragma unroll
            for (int q = 0; q < 4; ++q) c[m][n][q] = 0.0f;

    LOADST(0, 0); CP_COMMIT();
    LOADST(1, 1); CP_COMMIT();

    for (int kt = 0; kt < NKCH; ++kt) {
        const int cur = kt & 1;
        CP_WAIT1();
        __syncthreads();
        const uint32_t st  = sb + cur*4*TB;
        const uint32_t tAh = st,        tAl = st + TB;
        const uint32_t tBh = st + 2*TB, tBl = st + 3*TB;
#pragma unroll
        for (int kk = 0; kk < 4; ++kk) {
            const uint32_t kb = kk * 32;
            uint32_t bh[4][2], bl[4][2];
#pragma unroll
            for (int n = 0; n < 4; ++n) {
                uint32_t bo = sw((b_row + n*8)*128 + kb + b_kb);
                LDSM2(bh[n][0], bh[n][1], tBh + bo);
                LDSM2(bl[n][0], bl[n][1], tBl + bo);
            }
#pragma unroll
            for (int m = 0; m < 4; ++m) {
                uint32_t ao = sw((a_row + m*16)*128 + kb + a_kb);
                uint32_t ah[4], al[4];
                LDSM4(ah[0], ah[1], ah[2], ah[3], tAh + ao);
                LDSM4(al[0], al[1], al[2], al[3], tAl + ao);
#pragma unroll
                for (int n = 0; n < 4; ++n) {
                    MMA(c[m][n], ah, bh[n]);
                    MMA(c[m][n], ah, bl[n]);
                    MMA(c[m][n], al, bh[n]);
                }
            }
        }
        __syncthreads();
        if (kt + 2 < NKCH) LOADST(cur, kt + 2);
        CP_COMMIT();
    }
#undef LOADST

    // ---- epilogue
    const int rbase = wm*64 + (lane >> 2);
    const int cbase = by*128 + wn*32 + (lane & 3)*2;
#pragma unroll
    for (int m = 0; m < 4; ++m) {
#pragma unroll
        for (int half = 0; half < 2; ++half) {
            const int rloc = rbase + m*16 + half*8;
            if (rloc >= rows) continue;
            const size_t grow = (size_t)(rs + rloc);
#pragma unroll
            for (int n = 0; n < 4; ++n) {
                float v0 = c[m][n][half*2], v1 = c[m][n][half*2 + 1];
                const size_t col = cbase + n*8;
                if (MODE == 0) {
                    *(float2*)(g_h0 + grow*IDIM + col) = make_float2(v0, v1);
                } else if (MODE == 1) {
                    float2 h = *(const float2*)(g_h0 + grow*IDIM + col);
                    float o0 = h.x / (1.0f + __expf(-h.x)) * v0;
                    float o1 = h.y / (1.0f + __expf(-h.y)) * v1;
                    __nv_bfloat162 hh = __floats2bfloat162_rn(o0, o1);
                    __nv_bfloat162 ll = __floats2bfloat162_rn(
                        o0 - __bfloat162float(hh.x), o1 - __bfloat162float(hh.y));
                    *(__nv_bfloat162*)(g_ih + grow*IDIM + col) = hh;
                    *(__nv_bfloat162*)(g_il + grow*IDIM + col) = ll;
                } else {
                    *(float2*)(g_op + grow*DIM + col) = make_float2(v0, v1);
                }
            }
        }
    }
}

// ---------------- launch ----------------
extern "C" void kernel_launch(void* const* d_in, const int* in_sizes, int n_in,
                              void* d_out, int out_size) {
    const float* inputs = (const float*)d_in[0];
    const float* logits = (const float*)d_in[1];
    const float* wi0    = (const float*)d_in[2];
    const float* wi1    = (const float*)d_in[3];
    const float* wo     = (const float*)d_in[4];
    float* out = (float*)d_out;

    cudaFuncSetAttribute(k_mma<0>, cudaFuncAttributeMaxDynamicSharedMemorySize, GSMEM);
    cudaFuncSetAttribute(k_mma<1>, cudaFuncAttributeMaxDynamicSharedMemorySize, GSMEM);
    cudaFuncSetAttribute(k_mma<2>, cudaFuncAttributeMaxDynamicSharedMemorySize, GSMEM);

    k_reset<<<1, 32>>>();
    k_router<<<T_TOK/256, 256>>>(logits);
    k_schedule<<<1, 1>>>();
    k_scatter<<<NPAIR/256, 256>>>();
    k_permx<<<NPAIR, 256>>>(inputs);
    dim3 cw(64, 64, 8);
    k_convw<0><<<cw, 256>>>(wi0);
    k_convw<1><<<cw, 256>>>(wi1);
    k_convw<2><<<cw, 256>>>(wo);
    dim3 gg(NTMAX, 16);
    k_mma<0><<<gg, 256, GSMEM>>>();
    k_mma<1><<<gg, 256, GSMEM>>>();
    k_mma<2><<<gg, 256, GSMEM>>>();
    k_combine<<<T_TOK, 256>>>(out);
}

// round 5
// speedup vs baseline: 2.9331x; 1.3090x over previous
#include <cuda_runtime.h>
#include <cuda_bf16.h>
#include <math.h>
#include <stdint.h>

#define T_TOK 8192
#define DIM   2048
#define IDIM  2048
#define NEXP  8
#define NPAIR 16384
#define NTMAX 136
#define KC    32
#define NKT   64            // 2048 / 32
#define TBS   8192          // 128 rows x 32k x 2B (64B rows)
#define SM12  (4*6*TBS)     // 192 KB
#define SM3   (4*4*TBS)     // 128 KB

// ---------------- device scratch ----------------
__device__ int   g_expert[NPAIR];
__device__ float g_weight[NPAIR];
__device__ int   g_cnt[NEXP], g_cursor[NEXP];
__device__ int   g_pos[NPAIR];
__device__ int   g_tstart[NTMAX], g_texp[NTMAX], g_trows[NTMAX];
__device__ int   g_flag;
__device__ __align__(16) __nv_bfloat16 g_xph[(size_t)NPAIR*DIM];
__device__ __align__(16) __nv_bfloat16 g_xpl[(size_t)NPAIR*DIM];
__device__ __align__(16) __nv_bfloat16 g_w0h[(size_t)NEXP*DIM*IDIM];
__device__ __align__(16) __nv_bfloat16 g_w0l[(size_t)NEXP*DIM*IDIM];
__device__ __align__(16) __nv_bfloat16 g_w1h[(size_t)NEXP*DIM*IDIM];
__device__ __align__(16) __nv_bfloat16 g_w1l[(size_t)NEXP*DIM*IDIM];
__device__ __align__(16) __nv_bfloat16 g_woh[(size_t)NEXP*DIM*IDIM];
__device__ __align__(16) __nv_bfloat16 g_wol[(size_t)NEXP*DIM*IDIM];
__device__ __align__(16) __nv_bfloat16 g_ih[(size_t)NPAIR*IDIM];
__device__ __align__(16) __nv_bfloat16 g_il[(size_t)NPAIR*IDIM];
__device__ __align__(16) float g_op[(size_t)NPAIR*DIM];

// ---------------- helpers ----------------
__device__ __forceinline__ uint32_t s2u(const void* p) {
    uint32_t a;
    asm("{ .reg .u64 t; cvta.to.shared.u64 t, %1; cvt.u32.u64 %0, t; }" : "=r"(a) : "l"(p));
    return a;
}
__device__ __forceinline__ uint32_t sw64(uint32_t o) { return o ^ ((o >> 3) & 0x30); }

#define CP16(dst, src) asm volatile("cp.async.cg.shared.global [%0], [%1], 16;" \
                                    :: "r"(dst), "l"(src) : "memory")
#define CP_COMMIT() asm volatile("cp.async.commit_group;" ::: "memory")
#define CP_WAIT2()  asm volatile("cp.async.wait_group 2;" ::: "memory")

#define LDSM4(r0,r1,r2,r3,a) asm volatile( \
    "ldmatrix.sync.aligned.m8n8.x4.shared.b16 {%0,%1,%2,%3}, [%4];" \
    : "=r"(r0),"=r"(r1),"=r"(r2),"=r"(r3) : "r"(a))
#define LDSM2(r0,r1,a) asm volatile( \
    "ldmatrix.sync.aligned.m8n8.x2.shared.b16 {%0,%1}, [%2];" \
    : "=r"(r0),"=r"(r1) : "r"(a))
#define MMA(cc, A, B) asm volatile( \
    "mma.sync.aligned.m16n8k16.row.col.f32.bf16.bf16.f32 " \
    "{%0,%1,%2,%3}, {%4,%5,%6,%7}, {%8,%9}, {%0,%1,%2,%3};" \
    : "+f"(cc[0]),"+f"(cc[1]),"+f"(cc[2]),"+f"(cc[3]) \
    : "r"(A[0]),"r"(A[1]),"r"(A[2]),"r"(A[3]),"r"(B[0]),"r"(B[1]))

// ---------------- conversion: W[e][k][n] fp32 -> T[e][n][k] bf16 hi/lo ------
__global__ void k_convw(const float* __restrict__ W0, const float* __restrict__ W1,
                        const float* __restrict__ WO) {
    __shared__ float s[32][33];
    int z = blockIdx.z;
    int wsel = z >> 3, e = z & 7;
    const float* W = (wsel == 0) ? W0 : (wsel == 1) ? W1 : WO;
    __nv_bfloat16* Th = (wsel == 0) ? g_w0h : (wsel == 1) ? g_w1h : g_woh;
    __nv_bfloat16* Tl = (wsel == 0) ? g_w0l : (wsel == 1) ? g_w1l : g_wol;
    int k0 = blockIdx.x * 32, n0 = blockIdx.y * 32;
    const float* src = W + (size_t)e * DIM * IDIM;
    int tx = threadIdx.x & 31, ty = threadIdx.x >> 5;
#pragma unroll
    for (int i = 0; i < 4; ++i)
        s[ty + i*8][tx] = src[(size_t)(k0 + ty + i*8) * IDIM + n0 + tx];
    __syncthreads();
#pragma unroll
    for (int i = 0; i < 4; ++i) {
        int n = n0 + ty + i*8, k = k0 + tx;
        float x = s[tx][ty + i*8];
        __nv_bfloat16 h = __float2bfloat16_rn(x);
        size_t o = (size_t)e * DIM * IDIM + (size_t)n * DIM + k;
        Th[o] = h;
        Tl[o] = __float2bfloat16_rn(x - __bfloat162float(h));
    }
}

// ---------------- router ----------------
__global__ void k_router(const float* __restrict__ logits) {
    int t = blockIdx.x * blockDim.x + threadIdx.x;
    if (t >= T_TOK) return;
    const float* l = logits + t * NEXP;
    float v1 = -1e30f, v2 = -1e30f; int i1 = 0, i2 = 0;
#pragma unroll
    for (int e = 0; e < NEXP; ++e) {
        float v = l[e];
        if (v > v1)      { v2 = v1; i2 = i1; v1 = v; i1 = e; }
        else if (v > v2) { v2 = v;  i2 = e; }
    }
    float p = expf(v2 - v1);
    float s = 1.0f + p;
    float w1 = 1.0f / s, w2 = p / s;
    float sn = w1 + w2; w1 /= sn; w2 /= sn;
    g_expert[2*t] = i1; g_expert[2*t+1] = i2;
    g_weight[2*t] = w1; g_weight[2*t+1] = w2;
    atomicAdd(&g_cnt[i1], 1);
    atomicAdd(&g_cnt[i2], 1);
}

// ---------------- prep: schedule + scatter + permute/split ----------------
__global__ void k_prep(const float* __restrict__ X) {
    __shared__ int s_dst;
    if (blockIdx.x == 0 && threadIdx.x == 0) {
        int off = 0, nt = 0;
        for (int e = 0; e < NEXP; ++e) {
            int c = g_cnt[e];
            g_cursor[e] = off;
            for (int s = 0; s < c; s += 128) {
                g_tstart[nt] = off + s; g_texp[nt] = e;
                g_trows[nt] = (c - s < 128) ? (c - s) : 128; nt++;
            }
            off += c;
        }
        for (int i = nt; i < NTMAX; ++i) g_trows[i] = 0;
        __threadfence();
        atomicExch(&g_flag, 1);
    }
    if (threadIdx.x == 0) {
        while (atomicAdd(&g_flag, 0) == 0) {}
        int p = blockIdx.x;
        int dst = atomicAdd(&g_cursor[g_expert[p]], 1);
        g_pos[p] = dst;
        s_dst = dst;
    }
    __syncthreads();
    int p = blockIdx.x;
    int dst = s_dst;
    const float4* src = (const float4*)(X + (size_t)(p >> 1) * DIM);
    __nv_bfloat162* dh = (__nv_bfloat162*)(g_xph + (size_t)dst * DIM);
    __nv_bfloat162* dl = (__nv_bfloat162*)(g_xpl + (size_t)dst * DIM);
#pragma unroll
    for (int i = 0; i < 4; ++i) {
        int c = threadIdx.x + i * 128;
        float4 v = src[c];
        __nv_bfloat162 h0 = __floats2bfloat162_rn(v.x, v.y);
        __nv_bfloat162 h1 = __floats2bfloat162_rn(v.z, v.w);
        dh[2*c]   = h0;
        dh[2*c+1] = h1;
        dl[2*c]   = __floats2bfloat162_rn(v.x - __bfloat162float(h0.x),
                                          v.y - __bfloat162float(h0.y));
        dl[2*c+1] = __floats2bfloat162_rn(v.z - __bfloat162float(h1.x),
                                          v.w - __bfloat162float(h1.y));
    }
}

// ---------------- fused GEMM1+2: h0,h1 then inter=silu(h0)*h1 -> bf16 hi/lo --
__global__ void __launch_bounds__(256, 1) k_gemm12() {
    extern __shared__ char smem[];
    const int tid = threadIdx.x, lane = tid & 31, wid = tid >> 5;
    const int bx = blockIdx.x, by = blockIdx.y;
    const int rows = g_trows[bx];
    if (rows == 0) return;
    const int rs = g_tstart[bx], e = g_texp[bx];
    const uint32_t sb = s2u(smem);
    const size_t eo = (size_t)e * DIM * IDIM;
    const __nv_bfloat16 *B0h = g_w0h + eo, *B0l = g_w0l + eo;
    const __nv_bfloat16 *B1h = g_w1h + eo, *B1l = g_w1l + eo;

    // loader geometry: 2 x 16B per tile per thread
    const int r0 = tid >> 2, u0 = tid & 3;
    const int r1 = (tid + 256) >> 2, u1 = tid & 3;
    const uint32_t d0 = sw64(r0*64 + u0*16), d1 = sw64(r1*64 + u1*16);
    int ar0 = rs + r0; if (ar0 >= NPAIR) ar0 = NPAIR - 1;
    int ar1 = rs + r1; if (ar1 >= NPAIR) ar1 = NPAIR - 1;
    const size_t a0 = (size_t)ar0*2048 + u0*8, a1 = (size_t)ar1*2048 + u1*8;
    const size_t b0 = (size_t)(by*128 + r0)*2048 + u0*8;
    const size_t b1 = (size_t)(by*128 + r1)*2048 + u1*8;

#define ISSUE12(kt) { uint32_t st = sb + ((kt) & 3)*6*TBS; size_t k0 = (size_t)(kt)*KC; \
        CP16(st         + d0, g_xph + a0 + k0); CP16(st         + d1, g_xph + a1 + k0); \
        CP16(st +   TBS + d0, g_xpl + a0 + k0); CP16(st +   TBS + d1, g_xpl + a1 + k0); \
        CP16(st + 2*TBS + d0, B0h   + b0 + k0); CP16(st + 2*TBS + d1, B0h   + b1 + k0); \
        CP16(st + 3*TBS + d0, B0l   + b0 + k0); CP16(st + 3*TBS + d1, B0l   + b1 + k0); \
        CP16(st + 4*TBS + d0, B1h   + b0 + k0); CP16(st + 4*TBS + d1, B1h   + b1 + k0); \
        CP16(st + 5*TBS + d0, B1l   + b0 + k0); CP16(st + 5*TBS + d1, B1l   + b1 + k0); }

    // mma geometry: warp (wm, wn), warp tile 64x32
    const int wm = wid & 1, wn = wid >> 1;
    const uint32_t a_row = wm*64 + (lane & 15);
    const uint32_t a_kb  = ((lane >> 4) & 1) * 16;
    const int lb = lane & 15;
    const uint32_t b_row = wn*32 + (lb & 7);
    const uint32_t b_kb  = ((lb >> 3) & 1) * 16;

    float c0[4][4][4], c1[4][4][4];
#pragma unroll
    for (int m = 0; m < 4; ++m)
#pragma unroll
        for (int n = 0; n < 4; ++n)
#pragma unroll
            for (int q = 0; q < 4; ++q) { c0[m][n][q] = 0.f; c1[m][n][q] = 0.f; }

    ISSUE12(0); CP_COMMIT();
    ISSUE12(1); CP_COMMIT();
    ISSUE12(2); CP_COMMIT();

    for (int kt = 0; kt < NKT; ++kt) {
        CP_WAIT2();
        __syncthreads();
        if (kt + 3 < NKT) ISSUE12(kt + 3);
        CP_COMMIT();
        const uint32_t st = sb + (kt & 3)*6*TBS;
#pragma unroll
        for (int kk = 0; kk < 2; ++kk) {
            const uint32_t kb = kk * 32;
            uint32_t f0h[4][2], f0l[4][2], f1h[4][2], f1l[4][2];
#pragma unroll
            for (int n = 0; n < 4; ++n) {
                uint32_t bo = sw64((b_row + n*8)*64 + kb + b_kb);
                LDSM2(f0h[n][0], f0h[n][1], st + 2*TBS + bo);
                LDSM2(f0l[n][0], f0l[n][1], st + 3*TBS + bo);
                LDSM2(f1h[n][0], f1h[n][1], st + 4*TBS + bo);
                LDSM2(f1l[n][0], f1l[n][1], st + 5*TBS + bo);
            }
#pragma unroll
            for (int m = 0; m < 4; ++m) {
                uint32_t ao = sw64((a_row + m*16)*64 + kb + a_kb);
                uint32_t ah[4], al[4];
                LDSM4(ah[0], ah[1], ah[2], ah[3], st + ao);
                LDSM4(al[0], al[1], al[2], al[3], st + TBS + ao);
#pragma unroll
                for (int n = 0; n < 4; ++n) {
                    MMA(c0[m][n], ah, f0h[n]);
                    MMA(c0[m][n], ah, f0l[n]);
                    MMA(c0[m][n], al, f0h[n]);
                    MMA(c1[m][n], ah, f1h[n]);
                    MMA(c1[m][n], ah, f1l[n]);
                    MMA(c1[m][n], al, f1h[n]);
                }
            }
        }
    }
#undef ISSUE12

    // epilogue: inter = silu(h0) * h1 -> bf16 hi/lo
    const int rbase = wm*64 + (lane >> 2);
    const int cbase = by*128 + wn*32 + (lane & 3)*2;
#pragma unroll
    for (int m = 0; m < 4; ++m) {
#pragma unroll
        for (int half = 0; half < 2; ++half) {
            const int rloc = rbase + m*16 + half*8;
            if (rloc >= rows) continue;
            const size_t grow = (size_t)(rs + rloc);
#pragma unroll
            for (int n = 0; n < 4; ++n) {
                float h0a = c0[m][n][half*2], h0b = c0[m][n][half*2+1];
                float h1a = c1[m][n][half*2], h1b = c1[m][n][half*2+1];
                float o0 = h0a / (1.0f + expf(-h0a)) * h1a;
                float o1 = h0b / (1.0f + expf(-h0b)) * h1b;
                __nv_bfloat162 hh = __floats2bfloat162_rn(o0, o1);
                __nv_bfloat162 ll = __floats2bfloat162_rn(
                    o0 - __bfloat162float(hh.x), o1 - __bfloat162float(hh.y));
                const size_t col = cbase + n*8;
                *(__nv_bfloat162*)(g_ih + grow*IDIM + col) = hh;
                *(__nv_bfloat162*)(g_il + grow*IDIM + col) = ll;
            }
        }
    }
}

// ---------------- GEMM3: op = inter @ wo^T ----------------
__global__ void __launch_bounds__(256, 1) k_gemm3() {
    extern __shared__ char smem[];
    const int tid = threadIdx.x, lane = tid & 31, wid = tid >> 5;
    const int bx = blockIdx.x, by = blockIdx.y;
    const int rows = g_trows[bx];
    if (rows == 0) return;
    const int rs = g_tstart[bx], e = g_texp[bx];
    const uint32_t sb = s2u(smem);
    const size_t eo = (size_t)e * DIM * IDIM;
    const __nv_bfloat16 *Bh = g_woh + eo, *Bl = g_wol + eo;

    const int r0 = tid >> 2, u0 = tid & 3;
    const int r1 = (tid + 256) >> 2, u1 = tid & 3;
    const uint32_t d0 = sw64(r0*64 + u0*16), d1 = sw64(r1*64 + u1*16);
    int ar0 = rs + r0; if (ar0 >= NPAIR) ar0 = NPAIR - 1;
    int ar1 = rs + r1; if (ar1 >= NPAIR) ar1 = NPAIR - 1;
    const size_t a0 = (size_t)ar0*2048 + u0*8, a1 = (size_t)ar1*2048 + u1*8;
    const size_t b0 = (size_t)(by*128 + r0)*2048 + u0*8;
    const size_t b1 = (size_t)(by*128 + r1)*2048 + u1*8;

#define ISSUE3(kt) { uint32_t st = sb + ((kt) & 3)*4*TBS; size_t k0 = (size_t)(kt)*KC; \
        CP16(st         + d0, g_ih + a0 + k0); CP16(st         + d1, g_ih + a1 + k0); \
        CP16(st +   TBS + d0, g_il + a0 + k0); CP16(st +   TBS + d1, g_il + a1 + k0); \
        CP16(st + 2*TBS + d0, Bh   + b0 + k0); CP16(st + 2*TBS + d1, Bh   + b1 + k0); \
        CP16(st + 3*TBS + d0, Bl   + b0 + k0); CP16(st + 3*TBS + d1, Bl   + b1 + k0); }

    const int wm = wid & 1, wn = wid >> 1;
    const uint32_t a_row = wm*64 + (lane & 15);
    const uint32_t a_kb  = ((lane >> 4) & 1) * 16;
    const int lb = lane & 15;
    const uint32_t b_row = wn*32 + (lb & 7);
    const uint32_t b_kb  = ((lb >> 3) & 1) * 16;

    float c[4][4][4];
#pragma unroll
    for (int m = 0; m < 4; ++m)
#pragma unroll
        for (int n = 0; n < 4; ++n)
#pragma unroll
            for (int q = 0; q < 4; ++q) c[m][n][q] = 0.f;

    ISSUE3(0); CP_COMMIT();
    ISSUE3(1); CP_COMMIT();
    ISSUE3(2); CP_COMMIT();

    for (int kt = 0; kt < NKT; ++kt) {
        CP_WAIT2();
        __syncthreads();
        if (kt + 3 < NKT) ISSUE3(kt + 3);
        CP_COMMIT();
        const uint32_t st = sb + (kt & 3)*4*TBS;
#pragma unroll
        for (int kk = 0; kk < 2; ++kk) {
            const uint32_t kb = kk * 32;
            uint32_t fh[4][2], fl[4][2];
#pragma unroll
            for (int n = 0; n < 4; ++n) {
                uint32_t bo = sw64((b_row + n*8)*64 + kb + b_kb);
                LDSM2(fh[n][0], fh[n][1], st + 2*TBS + bo);
                LDSM2(fl[n][0], fl[n][1], st + 3*TBS + bo);
            }
#pragma unroll
            for (int m = 0; m < 4; ++m) {
                uint32_t ao = sw64((a_row + m*16)*64 + kb + a_kb);
                uint32_t ah[4], al[4];
                LDSM4(ah[0], ah[1], ah[2], ah[3], st + ao);
                LDSM4(al[0], al[1], al[2], al[3], st + TBS + ao);
#pragma unroll
                for (int n = 0; n < 4; ++n) {
                    MMA(c[m][n], ah, fh[n]);
                    MMA(c[m][n], ah, fl[n]);
                    MMA(c[m][n], al, fh[n]);
                }
            }
        }
    }
#undef ISSUE3

    const int rbase = wm*64 + (lane >> 2);
    const int cbase = by*128 + wn*32 + (lane & 3)*2;
#pragma unroll
    for (int m = 0; m < 4; ++m) {
#pragma unroll
        for (int half = 0; half < 2; ++half) {
            const int rloc = rbase + m*16 + half*8;
            if (rloc >= rows) continue;
            const size_t grow = (size_t)(rs + rloc);
#pragma unroll
            for (int n = 0; n < 4; ++n)
                *(float2*)(g_op + grow*DIM + cbase + n*8) =
                    make_float2(c[m][n][half*2], c[m][n][half*2+1]);
        }
    }
}

// ---------------- combine (+ state reset for next replay) ----------------
__global__ void k_combine(float* __restrict__ out) {
    int t = blockIdx.x;
    float w0 = g_weight[2*t], w1 = g_weight[2*t+1];
    const float4* r0 = (const float4*)(g_op + (size_t)g_pos[2*t]   * DIM);
    const float4* r1 = (const float4*)(g_op + (size_t)g_pos[2*t+1] * DIM);
    float4* o = (float4*)(out + (size_t)t * DIM);
    for (int c = threadIdx.x; c < DIM/4; c += blockDim.x) {
        float4 a = r0[c], b = r1[c];
        o[c] = make_float4(w0*a.x + w1*b.x, w0*a.y + w1*b.y,
                           w0*a.z + w1*b.z, w0*a.w + w1*b.w);
    }
    if (blockIdx.x == 0 && threadIdx.x < NEXP) g_cnt[threadIdx.x] = 0;
    if (blockIdx.x == 0 && threadIdx.x == 0)   g_flag = 0;
}

// ---------------- launch ----------------
extern "C" void kernel_launch(void* const* d_in, const int* in_sizes, int n_in,
                              void* d_out, int out_size) {
    const float* inputs = (const float*)d_in[0];
    const float* logits = (const float*)d_in[1];
    const float* wi0    = (const float*)d_in[2];
    const float* wi1    = (const float*)d_in[3];
    const float* wo     = (const float*)d_in[4];
    float* out = (float*)d_out;

    cudaFuncSetAttribute(k_gemm12, cudaFuncAttributeMaxDynamicSharedMemorySize, SM12);
    cudaFuncSetAttribute(k_gemm3,  cudaFuncAttributeMaxDynamicSharedMemorySize, SM3);

    k_convw<<<dim3(64, 64, 24), 256>>>(wi0, wi1, wo);      // 0
    k_router<<<T_TOK/256, 256>>>(logits);                  // 1
    k_prep<<<NPAIR, 128>>>(inputs);                        // 2
    k_gemm12<<<dim3(NTMAX, IDIM/128), 256, SM12>>>();      // 3  <- ncu slot
    k_gemm3 <<<dim3(NTMAX, DIM/128),  256, SM3>>>();       // 4
    k_combine<<<T_TOK, 256>>>(out);                        // 5
}

// round 6
// speedup vs baseline: 3.0541x; 1.0413x over previous
#include <cuda_runtime.h>
#include <cuda_bf16.h>
#include <math.h>
#include <stdint.h>

#define T_TOK 8192
#define DIM   2048
#define IDIM  2048
#define NEXP  8
#define NPAIR 16384
#define NTMAX 136
#define KC    32
#define NKT   64            // 2048 / 32
#define TBS   8192          // 128 rows x 32k x 2B (64B rows)
#define SM12  (4*6*TBS)     // 192 KB, 4-stage ring
#define SM3   (3*4*TBS)     // 96 KB, 3-stage ring
#define EPAD  144           // epilogue smem row stride (floats)

// ---------------- device scratch ----------------
__device__ int   g_expert[NPAIR];
__device__ float g_weight[NPAIR];
__device__ int   g_cnt[NEXP], g_cursor[NEXP];
__device__ int   g_pos[NPAIR];
__device__ int   g_tstart[NTMAX], g_texp[NTMAX], g_trows[NTMAX];
__device__ int   g_flag;
__device__ __align__(16) __nv_bfloat16 g_xph[(size_t)NPAIR*DIM];
__device__ __align__(16) __nv_bfloat16 g_xpl[(size_t)NPAIR*DIM];
__device__ __align__(16) __nv_bfloat16 g_w0h[(size_t)NEXP*DIM*IDIM];
__device__ __align__(16) __nv_bfloat16 g_w0l[(size_t)NEXP*DIM*IDIM];
__device__ __align__(16) __nv_bfloat16 g_w1h[(size_t)NEXP*DIM*IDIM];
__device__ __align__(16) __nv_bfloat16 g_w1l[(size_t)NEXP*DIM*IDIM];
__device__ __align__(16) __nv_bfloat16 g_woh[(size_t)NEXP*DIM*IDIM];
__device__ __align__(16) __nv_bfloat16 g_wol[(size_t)NEXP*DIM*IDIM];
__device__ __align__(16) __nv_bfloat16 g_ih[(size_t)NPAIR*IDIM];
__device__ __align__(16) __nv_bfloat16 g_il[(size_t)NPAIR*IDIM];
__device__ __align__(16) float g_op[(size_t)NPAIR*DIM];

// ---------------- helpers ----------------
__device__ __forceinline__ uint32_t s2u(const void* p) {
    uint32_t a;
    asm("{ .reg .u64 t; cvta.to.shared.u64 t, %1; cvt.u32.u64 %0, t; }" : "=r"(a) : "l"(p));
    return a;
}
__device__ __forceinline__ uint32_t sw64(uint32_t o) { return o ^ ((o >> 3) & 0x30); }

#define CP16(dst, src) asm volatile("cp.async.cg.shared.global [%0], [%1], 16;" \
                                    :: "r"(dst), "l"(src) : "memory")
#define CP_COMMIT() asm volatile("cp.async.commit_group;" ::: "memory")
#define CP_WAITN(n) asm volatile("cp.async.wait_group %0;" :: "n"(n) : "memory")

#define LDSM4(r0,r1,r2,r3,a) asm volatile( \
    "ldmatrix.sync.aligned.m8n8.x4.shared.b16 {%0,%1,%2,%3}, [%4];" \
    : "=r"(r0),"=r"(r1),"=r"(r2),"=r"(r3) : "r"(a))
#define LDSM2(r0,r1,a) asm volatile( \
    "ldmatrix.sync.aligned.m8n8.x2.shared.b16 {%0,%1}, [%2];" \
    : "=r"(r0),"=r"(r1) : "r"(a))
#define MMA(cc, A, B) asm volatile( \
    "mma.sync.aligned.m16n8k16.row.col.f32.bf16.bf16.f32 " \
    "{%0,%1,%2,%3}, {%4,%5,%6,%7}, {%8,%9}, {%0,%1,%2,%3};" \
    : "+f"(cc[0]),"+f"(cc[1]),"+f"(cc[2]),"+f"(cc[3]) \
    : "r"(A[0]),"r"(A[1]),"r"(A[2]),"r"(A[3]),"r"(B[0]),"r"(B[1]))

// ---------------- conversion: W[e][k][n] fp32 -> T[e][n][k] bf16 hi/lo ------
__global__ void k_convw(const float* __restrict__ W0, const float* __restrict__ W1,
                        const float* __restrict__ WO) {
    __shared__ float s[32][33];
    int z = blockIdx.z;
    int wsel = z >> 3, e = z & 7;
    const float* W = (wsel == 0) ? W0 : (wsel == 1) ? W1 : WO;
    __nv_bfloat16* Th = (wsel == 0) ? g_w0h : (wsel == 1) ? g_w1h : g_woh;
    __nv_bfloat16* Tl = (wsel == 0) ? g_w0l : (wsel == 1) ? g_w1l : g_wol;
    int k0 = blockIdx.x * 32, n0 = blockIdx.y * 32;
    const float* src = W + (size_t)e * DIM * IDIM;
    int tx = threadIdx.x & 31, ty = threadIdx.x >> 5;
#pragma unroll
    for (int i = 0; i < 4; ++i)
        s[ty + i*8][tx] = src[(size_t)(k0 + ty + i*8) * IDIM + n0 + tx];
    __syncthreads();
#pragma unroll
    for (int i = 0; i < 4; ++i) {
        int n = n0 + ty + i*8, k = k0 + tx;
        float x = s[tx][ty + i*8];
        __nv_bfloat16 h = __float2bfloat16_rn(x);
        size_t o = (size_t)e * DIM * IDIM + (size_t)n * DIM + k;
        Th[o] = h;
        Tl[o] = __float2bfloat16_rn(x - __bfloat162float(h));
    }
}

// ---------------- router ----------------
__global__ void k_router(const float* __restrict__ logits) {
    int t = blockIdx.x * blockDim.x + threadIdx.x;
    if (t >= T_TOK) return;
    const float* l = logits + t * NEXP;
    float v1 = -1e30f, v2 = -1e30f; int i1 = 0, i2 = 0;
#pragma unroll
    for (int e = 0; e < NEXP; ++e) {
        float v = l[e];
        if (v > v1)      { v2 = v1; i2 = i1; v1 = v; i1 = e; }
        else if (v > v2) { v2 = v;  i2 = e; }
    }
    float p = expf(v2 - v1);
    float s = 1.0f + p;
    float w1 = 1.0f / s, w2 = p / s;
    float sn = w1 + w2; w1 /= sn; w2 /= sn;
    g_expert[2*t] = i1; g_expert[2*t+1] = i2;
    g_weight[2*t] = w1; g_weight[2*t+1] = w2;
    atomicAdd(&g_cnt[i1], 1);
    atomicAdd(&g_cnt[i2], 1);
}

// ---------------- prep: schedule + scatter + permute/split ----------------
__global__ void k_prep(const float* __restrict__ X) {
    __shared__ int s_dst;
    if (blockIdx.x == 0 && threadIdx.x == 0) {
        int off = 0, nt = 0;
        for (int e = 0; e < NEXP; ++e) {
            int c = g_cnt[e];
            g_cursor[e] = off;
            for (int s = 0; s < c; s += 128) {
                g_tstart[nt] = off + s; g_texp[nt] = e;
                g_trows[nt] = (c - s < 128) ? (c - s) : 128; nt++;
            }
            off += c;
        }
        for (int i = nt; i < NTMAX; ++i) g_trows[i] = 0;
        __threadfence();
        atomicExch(&g_flag, 1);
    }
    if (threadIdx.x == 0) {
        while (atomicAdd(&g_flag, 0) == 0) {}
        int p = blockIdx.x;
        int dst = atomicAdd(&g_cursor[g_expert[p]], 1);
        g_pos[p] = dst;
        s_dst = dst;
    }
    __syncthreads();
    int p = blockIdx.x;
    int dst = s_dst;
    const float4* src = (const float4*)(X + (size_t)(p >> 1) * DIM);
    __nv_bfloat162* dh = (__nv_bfloat162*)(g_xph + (size_t)dst * DIM);
    __nv_bfloat162* dl = (__nv_bfloat162*)(g_xpl + (size_t)dst * DIM);
#pragma unroll
    for (int i = 0; i < 4; ++i) {
        int c = threadIdx.x + i * 128;
        float4 v = src[c];
        __nv_bfloat162 h0 = __floats2bfloat162_rn(v.x, v.y);
        __nv_bfloat162 h1 = __floats2bfloat162_rn(v.z, v.w);
        dh[2*c]   = h0;
        dh[2*c+1] = h1;
        dl[2*c]   = __floats2bfloat162_rn(v.x - __bfloat162float(h0.x),
                                          v.y - __bfloat162float(h0.y));
        dl[2*c+1] = __floats2bfloat162_rn(v.z - __bfloat162float(h1.x),
                                          v.w - __bfloat162float(h1.y));
    }
}

// ---------------- fused GEMM1+2, warp-specialized (512 threads) -------------
// warpgroup 0 (warps 0-7): h0 = Xp @ w0^T;  warpgroup 1 (warps 8-15): h1 = Xp @ w1^T
// shared SMEM A tiles; epilogue exchanges via smem, inter=silu(h0)*h1 -> bf16 hi/lo
__global__ void __launch_bounds__(512, 1) k_gemm12() {
    extern __shared__ char smem[];
    const int tid = threadIdx.x, lane = tid & 31, wid = tid >> 5;
    const int grp = wid >> 3, gid = wid & 7;
    const int bx = blockIdx.x, by = blockIdx.y;
    const int rows = g_trows[bx];
    if (rows == 0) return;
    const int rs = g_tstart[bx], e = g_texp[bx];
    const uint32_t sb = s2u(smem);
    const size_t eo = (size_t)e * DIM * IDIM;

    // loader geometry: 512 threads, one 16B unit per tile per stage
    const int lr = tid >> 2, lu = tid & 3;
    const uint32_t d0 = sw64(lr*64 + lu*16);
    int ar = rs + lr; if (ar >= NPAIR) ar = NPAIR - 1;
    const __nv_bfloat16* pxh = g_xph + (size_t)ar*2048 + lu*8;
    const __nv_bfloat16* pxl = g_xpl + (size_t)ar*2048 + lu*8;
    const size_t bofs = (size_t)(by*128 + lr)*2048 + lu*8;
    const __nv_bfloat16* p0h = g_w0h + eo + bofs;
    const __nv_bfloat16* p0l = g_w0l + eo + bofs;
    const __nv_bfloat16* p1h = g_w1h + eo + bofs;
    const __nv_bfloat16* p1l = g_w1l + eo + bofs;

#define ISSUE12(kt) { uint32_t st = sb + ((kt) & 3)*6*TBS; size_t k0 = (size_t)(kt)*KC; \
        CP16(st         + d0, pxh + k0); CP16(st +   TBS + d0, pxl + k0); \
        CP16(st + 2*TBS + d0, p0h + k0); CP16(st + 3*TBS + d0, p0l + k0); \
        CP16(st + 4*TBS + d0, p1h + k0); CP16(st + 5*TBS + d0, p1l + k0); }

    // mma geometry: within group, warp (wm, wn), warp tile 64x32
    const int wm = gid & 1, wn = gid >> 1;
    const uint32_t a_row = wm*64 + (lane & 15);
    const uint32_t a_kb  = ((lane >> 4) & 1) * 16;
    const int lb = lane & 15;
    const uint32_t b_row = wn*32 + (lb & 7);
    const uint32_t b_kb  = ((lb >> 3) & 1) * 16;
    const uint32_t bh_tile = (2 + 2*grp)*TBS;   // grp0: w0h, grp1: w1h
    const uint32_t bl_tile = (3 + 2*grp)*TBS;

    float c[4][4][4];
#pragma unroll
    for (int m = 0; m < 4; ++m)
#pragma unroll
        for (int n = 0; n < 4; ++n)
#pragma unroll
            for (int q = 0; q < 4; ++q) c[m][n][q] = 0.f;

    ISSUE12(0); CP_COMMIT();
    ISSUE12(1); CP_COMMIT();
    ISSUE12(2); CP_COMMIT();

    for (int kt = 0; kt < NKT; ++kt) {
        CP_WAITN(2);
        __syncthreads();
        if (kt + 3 < NKT) ISSUE12(kt + 3);
        CP_COMMIT();
        const uint32_t st = sb + (kt & 3)*6*TBS;
#pragma unroll
        for (int kk = 0; kk < 2; ++kk) {
            const uint32_t kb = kk * 32;
            uint32_t fh[4][2], fl[4][2];
#pragma unroll
            for (int n = 0; n < 4; ++n) {
                uint32_t bo = sw64((b_row + n*8)*64 + kb + b_kb);
                LDSM2(fh[n][0], fh[n][1], st + bh_tile + bo);
                LDSM2(fl[n][0], fl[n][1], st + bl_tile + bo);
            }
#pragma unroll
            for (int m = 0; m < 4; ++m) {
                uint32_t ao = sw64((a_row + m*16)*64 + kb + a_kb);
                uint32_t ah[4], al[4];
                LDSM4(ah[0], ah[1], ah[2], ah[3], st + ao);
                LDSM4(al[0], al[1], al[2], al[3], st + TBS + ao);
#pragma unroll
                for (int n = 0; n < 4; ++n) {
                    MMA(c[m][n], ah, fh[n]);
                    MMA(c[m][n], ah, fl[n]);
                    MMA(c[m][n], al, fh[n]);
                }
            }
        }
    }
#undef ISSUE12

    // ---- epilogue: exchange through smem, both groups combine half the rows
    __syncthreads();
    float* hs = (float*)smem;                       // [2][128][EPAD]
    float* mydst = hs + (size_t)grp * 128 * EPAD;
    const int rbase = wm*64 + (lane >> 2);
    const int cbase = wn*32 + (lane & 3)*2;
#pragma unroll
    for (int m = 0; m < 4; ++m)
#pragma unroll
        for (int half = 0; half < 2; ++half) {
            const int row = rbase + m*16 + half*8;
#pragma unroll
            for (int n = 0; n < 4; ++n)
                *(float2*)&mydst[row*EPAD + cbase + n*8] =
                    make_float2(c[m][n][half*2], c[m][n][half*2+1]);
        }
    __syncthreads();

    const int t = tid & 255;
    const int row = grp*64 + (t >> 2);
    if (row < rows) {
        const float* h0r = hs + row*EPAD;
        const float* h1r = hs + 128*EPAD + row*EPAD;
        const size_t gbase = (size_t)(rs + row) * IDIM + by*128;
        const int cb = (t & 3) * 4;
#pragma unroll
        for (int j = 0; j < 8; ++j) {
            const int col = cb + j*16;
            float4 a = *(const float4*)(h0r + col);
            float4 b = *(const float4*)(h1r + col);
            float o0 = a.x / (1.0f + expf(-a.x)) * b.x;
            float o1 = a.y / (1.0f + expf(-a.y)) * b.y;
            float o2 = a.z / (1.0f + expf(-a.z)) * b.z;
            float o3 = a.w / (1.0f + expf(-a.w)) * b.w;
            __nv_bfloat162 h01 = __floats2bfloat162_rn(o0, o1);
            __nv_bfloat162 h23 = __floats2bfloat162_rn(o2, o3);
            __nv_bfloat162 l01 = __floats2bfloat162_rn(
                o0 - __bfloat162float(h01.x), o1 - __bfloat162float(h01.y));
            __nv_bfloat162 l23 = __floats2bfloat162_rn(
                o2 - __bfloat162float(h23.x), o3 - __bfloat162float(h23.y));
            *(uint2*)(g_ih + gbase + col) = make_uint2(*(uint32_t*)&h01, *(uint32_t*)&h23);
            *(uint2*)(g_il + gbase + col) = make_uint2(*(uint32_t*)&l01, *(uint32_t*)&l23);
        }
    }
}

// ---------------- GEMM3: op = inter @ wo^T (3-stage, 2 CTAs/SM) -------------
__global__ void __launch_bounds__(256, 2) k_gemm3() {
    extern __shared__ char smem[];
    const int tid = threadIdx.x, lane = tid & 31, wid = tid >> 5;
    const int bx = blockIdx.x, by = blockIdx.y;
    const int rows = g_trows[bx];
    if (rows == 0) return;
    const int rs = g_tstart[bx], e = g_texp[bx];
    const uint32_t sb = s2u(smem);
    const size_t eo = (size_t)e * DIM * IDIM;

    const int r0 = tid >> 2, u0 = tid & 3;
    const int r1 = (tid + 256) >> 2;
    const uint32_t d0 = sw64(r0*64 + u0*16), d1 = sw64(r1*64 + u0*16);
    int ar0 = rs + r0; if (ar0 >= NPAIR) ar0 = NPAIR - 1;
    int ar1 = rs + r1; if (ar1 >= NPAIR) ar1 = NPAIR - 1;
    const size_t a0 = (size_t)ar0*2048 + u0*8, a1 = (size_t)ar1*2048 + u0*8;
    const size_t b0 = (size_t)(by*128 + r0)*2048 + u0*8;
    const size_t b1 = (size_t)(by*128 + r1)*2048 + u0*8;
    const __nv_bfloat16 *Bh = g_woh + eo, *Bl = g_wol + eo;

#define ISSUE3(kt) { uint32_t st = sb + ((kt) % 3)*4*TBS; size_t k0 = (size_t)(kt)*KC; \
        CP16(st         + d0, g_ih + a0 + k0); CP16(st         + d1, g_ih + a1 + k0); \
        CP16(st +   TBS + d0, g_il + a0 + k0); CP16(st +   TBS + d1, g_il + a1 + k0); \
        CP16(st + 2*TBS + d0, Bh   + b0 + k0); CP16(st + 2*TBS + d1, Bh   + b1 + k0); \
        CP16(st + 3*TBS + d0, Bl   + b0 + k0); CP16(st + 3*TBS + d1, Bl   + b1 + k0); }

    const int wm = wid & 1, wn = wid >> 1;
    const uint32_t a_row = wm*64 + (lane & 15);
    const uint32_t a_kb  = ((lane >> 4) & 1) * 16;
    const int lb = lane & 15;
    const uint32_t b_row = wn*32 + (lb & 7);
    const uint32_t b_kb  = ((lb >> 3) & 1) * 16;

    float c[4][4][4];
#pragma unroll
    for (int m = 0; m < 4; ++m)
#pragma unroll
        for (int n = 0; n < 4; ++n)
#pragma unroll
            for (int q = 0; q < 4; ++q) c[m][n][q] = 0.f;

    ISSUE3(0); CP_COMMIT();
    ISSUE3(1); CP_COMMIT();

    for (int kt = 0; kt < NKT; ++kt) {
        CP_WAITN(1);
        __syncthreads();
        if (kt + 2 < NKT) ISSUE3(kt + 2);
        CP_COMMIT();
        const uint32_t st = sb + (kt % 3)*4*TBS;
#pragma unroll
        for (int kk = 0; kk < 2; ++kk) {
            const uint32_t kb = kk * 32;
            uint32_t fh[4][2], fl[4][2];
#pragma unroll
            for (int n = 0; n < 4; ++n) {
                uint32_t bo = sw64((b_row + n*8)*64 + kb + b_kb);
                LDSM2(fh[n][0], fh[n][1], st + 2*TBS + bo);
                LDSM2(fl[n][0], fl[n][1], st + 3*TBS + bo);
            }
#pragma unroll
            for (int m = 0; m < 4; ++m) {
                uint32_t ao = sw64((a_row + m*16)*64 + kb + a_kb);
                uint32_t ah[4], al[4];
                LDSM4(ah[0], ah[1], ah[2], ah[3], st + ao);
                LDSM4(al[0], al[1], al[2], al[3], st + TBS + ao);
#pragma unroll
                for (int n = 0; n < 4; ++n) {
                    MMA(c[m][n], ah, fh[n]);
                    MMA(c[m][n], ah, fl[n]);
                    MMA(c[m][n], al, fh[n]);
                }
            }
        }
    }
#undef ISSUE3

    const int rbase = wm*64 + (lane >> 2);
    const int cbase = by*128 + wn*32 + (lane & 3)*2;
#pragma unroll
    for (int m = 0; m < 4; ++m)
#pragma unroll
        for (int half = 0; half < 2; ++half) {
            const int rloc = rbase + m*16 + half*8;
            if (rloc >= rows) continue;
            const size_t grow = (size_t)(rs + rloc);
#pragma unroll
            for (int n = 0; n < 4; ++n)
                *(float2*)(g_op + grow*DIM + cbase + n*8) =
                    make_float2(c[m][n][half*2], c[m][n][half*2+1]);
        }
}

// ---------------- combine (+ state reset for next replay) ----------------
__global__ void k_combine(float* __restrict__ out) {
    int t = blockIdx.x;
    float w0 = g_weight[2*t], w1 = g_weight[2*t+1];
    const float4* r0 = (const float4*)(g_op + (size_t)g_pos[2*t]   * DIM);
    const float4* r1 = (const float4*)(g_op + (size_t)g_pos[2*t+1] * DIM);
    float4* o = (float4*)(out + (size_t)t * DIM);
    for (int c = threadIdx.x; c < DIM/4; c += blockDim.x) {
        float4 a = r0[c], b = r1[c];
        o[c] = make_float4(w0*a.x + w1*b.x, w0*a.y + w1*b.y,
                           w0*a.z + w1*b.z, w0*a.w + w1*b.w);
    }
    if (blockIdx.x == 0 && threadIdx.x < NEXP) g_cnt[threadIdx.x] = 0;
    if (blockIdx.x == 0 && threadIdx.x == 0)   g_flag = 0;
}

// ---------------- launch ----------------
extern "C" void kernel_launch(void* const* d_in, const int* in_sizes, int n_in,
                              void* d_out, int out_size) {
    const float* inputs = (const float*)d_in[0];
    const float* logits = (const float*)d_in[1];
    const float* wi0    = (const float*)d_in[2];
    const float* wi1    = (const float*)d_in[3];
    const float* wo     = (const float*)d_in[4];
    float* out = (float*)d_out;

    cudaFuncSetAttribute(k_gemm12, cudaFuncAttributeMaxDynamicSharedMemorySize, SM12);
    cudaFuncSetAttribute(k_gemm3,  cudaFuncAttributeMaxDynamicSharedMemorySize, SM3);

    k_convw<<<dim3(64, 64, 24), 256>>>(wi0, wi1, wo);      // 0
    k_router<<<T_TOK/256, 256>>>(logits);                  // 1
    k_prep<<<NPAIR, 128>>>(inputs);                        // 2
    k_gemm12<<<dim3(NTMAX, IDIM/128), 512, SM12>>>();      // 3  <- ncu slot
    k_gemm3 <<<dim3(NTMAX, DIM/128),  256, SM3>>>();       // 4
    k_combine<<<T_TOK, 256>>>(out);                        // 5
}